// round 9
// baseline (speedup 1.0000x reference)
#include <cuda_runtime.h>
#include <cuda_bf16.h>
#include <cstdint>

#define D       512
#define NCLS    9
#define EPSF    1e-5f
#define E_PAD   150016   // 150000 padded to multiple of 128
#define CHUNKS  24       // 8 k-blocks x 3 split-products
#define STAGES  3
#define STG_B   32768u   // A 16KB + W 16KB per stage

// ---------------- scratch (bss; no runtime allocation) ---------------------
__device__ __align__(128) __nv_bfloat16 g_a[(size_t)E_PAD * 1024];   // A hi|lo
__device__ float g_h[(size_t)E_PAD * D];                             // GEMM fp32 out
__device__ __align__(128) __nv_bfloat16 g_w1p[512 * 1024];           // W1 hi|lo
__device__ __align__(128) __nv_bfloat16 g_w2p[512 * 1024];           // W2 hi|lo
__device__ float g_sum[D];
__device__ float g_sumsq[D];
__device__ float g_sc[D];
__device__ float g_sh[D];

// ======================= PTX helpers (sm_100-safe) ==========================
__device__ __forceinline__ uint32_t smem_to_u32(const void* p) {
    uint32_t a;
    asm("{ .reg .u64 t; cvta.to.shared.u64 t, %1; cvt.u32.u64 %0, t; }" : "=r"(a) : "l"(p));
    return a;
}
#define CP_ASYNC16(dst, src) \
    asm volatile("cp.async.cg.shared.global [%0], [%1], 16;" :: "r"(dst), "l"(src) : "memory")
#define CP_COMMIT() asm volatile("cp.async.commit_group;" ::: "memory")
#define LDM_X4(r, addr) \
    asm volatile("ldmatrix.sync.aligned.m8n8.x4.shared.b16 {%0,%1,%2,%3}, [%4];" \
        : "=r"((r)[0]), "=r"((r)[1]), "=r"((r)[2]), "=r"((r)[3]) : "r"(addr))
#define MMA_BF16(d, a, b0, b1) \
    asm volatile("mma.sync.aligned.m16n8k16.row.col.f32.bf16.bf16.f32 " \
        "{%0,%1,%2,%3}, {%4,%5,%6,%7}, {%8,%9}, {%0,%1,%2,%3};" \
        : "+f"((d)[0]), "+f"((d)[1]), "+f"((d)[2]), "+f"((d)[3]) \
        : "r"((a)[0]), "r"((a)[1]), "r"((a)[2]), "r"((a)[3]), "r"(b0), "r"(b1))

// ---------------- 1) gather + add + LayerNorm -> bf16 hi|lo ----------------
__global__ void gather_ln(const float* __restrict__ x,
                          const int* __restrict__ src,
                          const int* __restrict__ dst,
                          const float* __restrict__ lnw,
                          __nv_bfloat16* __restrict__ A, int E)
{
    __shared__ float sred[32];
    __shared__ float sbc;
    const int e = blockIdx.x;
    const int t = threadIdx.x;          // 128 threads, 4 floats each
    const size_t so = (size_t)src[e] * D;
    const size_t dofs = (size_t)dst[e] * D;

    float4 a = *(const float4*)(x + so + t * 4);
    float4 b = *(const float4*)(x + dofs + t * 4);
    float4 v = make_float4(a.x + b.x, a.y + b.y, a.z + b.z, a.w + b.w);

    const int lane = t & 31, wid = t >> 5;

    float s = v.x + v.y + v.z + v.w;
    #pragma unroll
    for (int o = 16; o; o >>= 1) s += __shfl_down_sync(0xffffffffu, s, o);
    if (lane == 0) sred[wid] = s;
    __syncthreads();
    if (t == 0) sbc = (sred[0] + sred[1] + sred[2] + sred[3]) * (1.0f / D);
    __syncthreads();
    const float mu = sbc;

    float dx = v.x - mu, dy = v.y - mu, dz = v.z - mu, dw = v.w - mu;
    float ss = dx * dx + dy * dy + dz * dz + dw * dw;
    __syncthreads();
    #pragma unroll
    for (int o = 16; o; o >>= 1) ss += __shfl_down_sync(0xffffffffu, ss, o);
    if (lane == 0) sred[wid] = ss;
    __syncthreads();
    if (t == 0) sbc = rsqrtf((sred[0] + sred[1] + sred[2] + sred[3]) * (1.0f / D) + EPSF);
    __syncthreads();
    const float rs = sbc;

    float4 w = *(const float4*)(lnw + t * 4);
    float vals[4] = { dx * rs * w.x, dy * rs * w.y, dz * rs * w.z, dw * rs * w.w };

    union { __nv_bfloat16 b[4]; uint2 u; } ph_, pl_;
    #pragma unroll
    for (int m = 0; m < 4; m++) {
        __nv_bfloat16 hi = __float2bfloat16(vals[m]);
        ph_.b[m] = hi;
        pl_.b[m] = __float2bfloat16(vals[m] - __bfloat162float(hi));
    }
    __nv_bfloat16* arow = A + (size_t)e * 1024;
    *(uint2*)(arow + 4 * t)       = ph_.u;
    *(uint2*)(arow + 512 + 4 * t) = pl_.u;
}

// ---------------- weight split: W[512,512] fp32 -> [512][1024] hi|lo -------
__global__ void wsplit(const float* __restrict__ W, __nv_bfloat16* __restrict__ Wp)
{
    const int idx = blockIdx.x * blockDim.x + threadIdx.x;   // 512*512 threads
    const int n = idx >> 9, k = idx & 511;
    float w = W[idx];
    __nv_bfloat16 hi = __float2bfloat16(w);
    __nv_bfloat16 lo = __float2bfloat16(w - __bfloat162float(hi));
    Wp[(size_t)n * 1024 + k]       = hi;
    Wp[(size_t)n * 1024 + 512 + k] = lo;
}

// ---------------- BN+ReLU apply + re-split for next GEMM ------------------
__global__ void bn_split(const float* __restrict__ H, __nv_bfloat16* __restrict__ A, int E)
{
    const int idx = blockIdx.x * blockDim.x + threadIdx.x;   // E*128 threads
    if (idx >= E * 128) return;
    const int r = idx >> 7;
    const int c = (idx & 127) * 4;
    float4 v = *(const float4*)(H + (size_t)r * D + c);
    float4 s4 = *(const float4*)(g_sc + c);
    float4 h4 = *(const float4*)(g_sh + c);
    float vals[4] = {
        fmaxf(fmaf(v.x, s4.x, h4.x), 0.0f), fmaxf(fmaf(v.y, s4.y, h4.y), 0.0f),
        fmaxf(fmaf(v.z, s4.z, h4.z), 0.0f), fmaxf(fmaf(v.w, s4.w, h4.w), 0.0f) };
    union { __nv_bfloat16 b[4]; uint2 u; } ph_, pl_;
    #pragma unroll
    for (int m = 0; m < 4; m++) {
        __nv_bfloat16 hi = __float2bfloat16(vals[m]);
        ph_.b[m] = hi;
        pl_.b[m] = __float2bfloat16(vals[m] - __bfloat162float(hi));
    }
    __nv_bfloat16* arow = A + (size_t)r * 1024;
    *(uint2*)(arow + c)       = ph_.u;
    *(uint2*)(arow + 512 + c) = pl_.u;
}

// ---------------- mma.sync GEMM + fused column stats -----------------------
// C[M,512] = (Ahi+Alo) @ (Whi+Wlo)^T ; also accumulates per-column
// sum / sumsq of C into g_sum / g_sumsq.
// 24 chunks of K=64: (hi,hi), (hi,lo), (lo,hi) per k-block j=0..7.
// CTA tile 128x128 with FOUR warps (2Mx2N of 64x64 warp tiles).
// 3-stage cp.async pipeline (32KB/stage), 2 CTAs/SM.
#define GEMM_SMEM (STAGES * 32768)

__global__ void __launch_bounds__(128, 2)
bgemm(const __nv_bfloat16* __restrict__ A, const __nv_bfloat16* __restrict__ W,
      float* __restrict__ C, int E)
{
    extern __shared__ __align__(128) char smem[];
    const int tid = threadIdx.x;
    const int lane = tid & 31, wid = tid >> 5;
    const int m0 = blockIdx.y * 128;
    const int n0 = blockIdx.x * 128;
    const uint32_t sbase = smem_to_u32(smem);

    // ---- cp.async mapping: 128 threads, 1 row each, 8 x 16B groups --------
    const __nv_bfloat16* Abase = A + (size_t)(m0 + tid) * 1024;
    const __nv_bfloat16* Wbase = W + (size_t)(n0 + tid) * 1024;
    uint32_t dsw[8];
    #pragma unroll
    for (int q = 0; q < 8; q++)
        dsw[q] = (uint32_t)(tid * 128 + (q ^ (tid & 7)) * 16);

    // ---- ldmatrix fragment addresses (warp 64x64) ----
    const int wm = (wid >> 1) * 64;       // warp M offset
    const int wn = (wid & 1) * 64;        // warp N offset
    const int ar = wm + (lane & 15);                       // + mf*16
    const int agsel = lane >> 4;
    const int br = wn + (lane & 7) + ((lane >> 4) << 3);   // + np*16
    const int bgsel = (lane >> 3) & 1;

    float acc[4][8][4];
    #pragma unroll
    for (int i = 0; i < 4; i++)
        #pragma unroll
        for (int j = 0; j < 8; j++)
            #pragma unroll
            for (int q = 0; q < 4; q++) acc[i][j][q] = 0.0f;

    // issue chunk i into stage st
    auto issue = [&](int i, int st) {
        const int j = i / 3, t3 = i - j * 3;
        const int ax = j * 64 + ((t3 == 2) ? 512 : 0);
        const int wx = j * 64 + ((t3 == 1) ? 512 : 0);
        const char* aps = (const char*)(Abase + ax);
        const char* wps = (const char*)(Wbase + wx);
        const uint32_t da = sbase + st * STG_B;
        const uint32_t dw = da + 16384u;
        #pragma unroll
        for (int q = 0; q < 8; q++) {
            CP_ASYNC16(da + dsw[q], aps + q * 16);
            CP_ASYNC16(dw + dsw[q], wps + q * 16);
        }
        CP_COMMIT();
    };

    auto compute = [&](int st) {
        const uint32_t sA = sbase + st * STG_B;
        const uint32_t sW = sA + 16384u;
        #pragma unroll
        for (int kk = 0; kk < 4; kk++) {
            const int kg2 = kk * 2;
            uint32_t a[4][4];
            #pragma unroll
            for (int mf = 0; mf < 4; mf++) {
                const int r = ar + mf * 16;
                const int g = kg2 + agsel;
                LDM_X4(a[mf], sA + r * 128 + ((g ^ (r & 7)) * 16));
            }
            #pragma unroll
            for (int np = 0; np < 4; np++) {
                const int r = br + np * 16;
                const int g = kg2 + bgsel;
                uint32_t b[4];
                LDM_X4(b, sW + r * 128 + ((g ^ (r & 7)) * 16));
                #pragma unroll
                for (int mf = 0; mf < 4; mf++) {
                    MMA_BF16(acc[mf][np * 2],     a[mf], b[0], b[1]);
                    MMA_BF16(acc[mf][np * 2 + 1], a[mf], b[2], b[3]);
                }
            }
        }
    };

    // ---- 3-stage mainloop: wait -> barrier -> issue(i+2) -> compute(i) ----
    issue(0, 0);
    issue(1, 1);
    #pragma unroll 1
    for (int i = 0; i < CHUNKS; i++) {
        if (i < CHUNKS - 1)
            asm volatile("cp.async.wait_group 1;" ::: "memory");
        else
            asm volatile("cp.async.wait_group 0;" ::: "memory");
        __syncthreads();
        if (i + 2 < CHUNKS) issue(i + 2, (i + 2) % STAGES);
        compute(i % STAGES);
    }

    // ---- epilogue: fragment -> global fp32 ----
    const int cq = (lane & 3) * 2;
    const int rq = lane >> 2;
    #pragma unroll
    for (int mf = 0; mf < 4; mf++) {
        const int r0 = m0 + wm + mf * 16 + rq;
        #pragma unroll
        for (int nf = 0; nf < 8; nf++) {
            const int col = n0 + wn + nf * 8 + cq;
            if (r0 < E)
                *(float2*)(C + (size_t)r0 * D + col) =
                    make_float2(acc[mf][nf][0], acc[mf][nf][1]);
            if (r0 + 8 < E)
                *(float2*)(C + (size_t)(r0 + 8) * D + col) =
                    make_float2(acc[mf][nf][2], acc[mf][nf][3]);
        }
    }

    // ---- fused BN column stats (rows >= E are exactly zero in A) ----------
    float* ssum = (float*)smem;          // 128 floats
    float* ssq  = (float*)smem + 128;    // 128 floats
    __syncthreads();                     // pipeline smem reads all done
    ssum[tid] = 0.0f; ssq[tid] = 0.0f;
    __syncthreads();

    #pragma unroll
    for (int nf = 0; nf < 8; nf++) {
        #pragma unroll
        for (int p = 0; p < 2; p++) {
            float s = 0.0f, q = 0.0f;
            #pragma unroll
            for (int mf = 0; mf < 4; mf++) {
                float v0 = acc[mf][nf][p], v1 = acc[mf][nf][p + 2];
                s += v0 + v1;
                q += v0 * v0 + v1 * v1;
            }
            #pragma unroll
            for (int mk = 4; mk <= 16; mk <<= 1) {
                s += __shfl_xor_sync(0xffffffffu, s, mk);
                q += __shfl_xor_sync(0xffffffffu, q, mk);
            }
            if (lane < 4) {
                const int cl = wn + nf * 8 + (lane & 3) * 2 + p;
                atomicAdd(&ssum[cl], s);
                atomicAdd(&ssq[cl], q);
            }
        }
    }
    __syncthreads();
    atomicAdd(&g_sum[n0 + tid], ssum[tid]);
    atomicAdd(&g_sumsq[n0 + tid], ssq[tid]);
}

// ---------------- stats setup / finalize -----------------------------------
__global__ void zero_stats()
{
    const int c = threadIdx.x;
    g_sum[c] = 0.0f;
    g_sumsq[c] = 0.0f;
}

__global__ void finalize_stats(const float* __restrict__ g,
                               const float* __restrict__ b, float invE)
{
    const int c = threadIdx.x;
    const float mean = g_sum[c] * invE;
    const float var  = g_sumsq[c] * invE - mean * mean;
    const float istd = rsqrtf(var + EPSF);
    const float scv  = istd * g[c];
    g_sc[c] = scv;
    g_sh[c] = fmaf(-mean, scv, b[c]);
}

// ---------------- head: out[E,9] = relu(BN(H)) @ Wout^T --------------------
__global__ void head(const float* __restrict__ H,
                     const float* __restrict__ Wout,
                     float* __restrict__ out, int E)
{
    __shared__ float Ws[NCLS * D];
    for (int i = threadIdx.x; i < NCLS * D; i += blockDim.x) Ws[i] = Wout[i];
    __syncthreads();

    const int warp = threadIdx.x >> 5, lane = threadIdx.x & 31;
    const int row = blockIdx.x * 8 + warp;
    if (row >= E) return;

    const float* hp = H + (size_t)row * D;
    float acc[NCLS];
    #pragma unroll
    for (int j = 0; j < NCLS; j++) acc[j] = 0.0f;

    #pragma unroll
    for (int i = 0; i < D / 32; i++) {
        const int k = lane + i * 32;
        const float v = fmaxf(fmaf(hp[k], g_sc[k], g_sh[k]), 0.0f);
        #pragma unroll
        for (int j = 0; j < NCLS; j++) acc[j] = fmaf(v, Ws[j * D + k], acc[j]);
    }
    #pragma unroll
    for (int j = 0; j < NCLS; j++)
        #pragma unroll
        for (int o = 16; o; o >>= 1)
            acc[j] += __shfl_down_sync(0xffffffffu, acc[j], o);

    if (lane == 0) {
        #pragma unroll
        for (int j = 0; j < NCLS; j++) out[(size_t)row * NCLS + j] = acc[j];
    }
}

// ---------------- launch ---------------------------------------------------
extern "C" void kernel_launch(void* const* d_in, const int* in_sizes, int n_in,
                              void* d_out, int out_size)
{
    const float* x    = (const float*)d_in[0];
    const int*   src  = (const int*)d_in[1];
    const int*   dst  = (const int*)d_in[2];
    const float* lnw  = (const float*)d_in[3];
    const float* W1   = (const float*)d_in[4];
    const float* g1   = (const float*)d_in[5];
    const float* b1   = (const float*)d_in[6];
    const float* W2   = (const float*)d_in[7];
    const float* g2   = (const float*)d_in[8];
    const float* b2   = (const float*)d_in[9];
    const float* Wout = (const float*)d_in[10];
    float* out = (float*)d_out;

    const int E = in_sizes[1];
    const float invE = 1.0f / (float)E;
    const int mtiles = (E + 127) / 128;

    void *pa, *phb, *pw1, *pw2;
    cudaGetSymbolAddress(&pa, g_a);
    cudaGetSymbolAddress(&phb, g_h);
    cudaGetSymbolAddress(&pw1, g_w1p);
    cudaGetSymbolAddress(&pw2, g_w2p);

    cudaFuncSetAttribute(bgemm, cudaFuncAttributeMaxDynamicSharedMemorySize, GEMM_SMEM);

    float* h = (float*)phb;
    __nv_bfloat16* A = (__nv_bfloat16*)pa;

    // 1) gather + LN -> A (bf16 hi|lo); weight splits
    gather_ln<<<E, 128>>>(x, src, dst, lnw, A, E);
    wsplit<<<512, 512>>>(W1, (__nv_bfloat16*)pw1);
    wsplit<<<512, 512>>>(W2, (__nv_bfloat16*)pw2);

    // 2) GEMM1 (+ fused BN1 stats): h = A @ W1^T
    zero_stats<<<1, D>>>();
    bgemm<<<dim3(4, mtiles), 128, GEMM_SMEM>>>(A, (__nv_bfloat16*)pw1, h, E);
    finalize_stats<<<1, D>>>(g1, b1, invE);

    // 3) BN1+ReLU apply + re-split -> A ; GEMM2 (+ fused BN2 stats)
    bn_split<<<(E * 128 + 255) / 256, 256>>>(h, A, E);
    zero_stats<<<1, D>>>();
    bgemm<<<dim3(4, mtiles), 128, GEMM_SMEM>>>(A, (__nv_bfloat16*)pw2, h, E);
    finalize_stats<<<1, D>>>(g2, b2, invE);

    // 4) head
    head<<<(E + 7) / 8, 256>>>(h, Wout, out, E);
}

// round 10
// speedup vs baseline: 2.6987x; 2.6987x over previous
#include <cuda_runtime.h>
#include <cuda_fp16.h>
#include <cstdint>

#define D       512
#define NCLS    9
#define EPSF    1e-5f
#define E_PAD   150016   // 150000 padded to multiple of 128
#define CHUNKS  8        // K=512 in chunks of 64
#define STAGES  3
#define STG_B   32768u   // A 16KB + W 16KB per stage

// ---------------- scratch (bss; no runtime allocation) ---------------------
__device__ __align__(128) __half g_a[(size_t)E_PAD * D];   // A fp16
__device__ float g_h[(size_t)E_PAD * D];                   // GEMM fp32 out
__device__ __align__(128) __half g_w1h[512 * 512];         // W1 fp16
__device__ __align__(128) __half g_w2h[512 * 512];         // W2 fp16
__device__ float g_sum[D];
__device__ float g_sumsq[D];
__device__ float g_sc[D];
__device__ float g_sh[D];

// ======================= PTX helpers (sm_100-safe) ==========================
__device__ __forceinline__ uint32_t smem_to_u32(const void* p) {
    uint32_t a;
    asm("{ .reg .u64 t; cvta.to.shared.u64 t, %1; cvt.u32.u64 %0, t; }" : "=r"(a) : "l"(p));
    return a;
}
#define CP_ASYNC16(dst, src) \
    asm volatile("cp.async.cg.shared.global [%0], [%1], 16;" :: "r"(dst), "l"(src) : "memory")
#define CP_COMMIT() asm volatile("cp.async.commit_group;" ::: "memory")
#define LDM_X4(r, addr) \
    asm volatile("ldmatrix.sync.aligned.m8n8.x4.shared.b16 {%0,%1,%2,%3}, [%4];" \
        : "=r"((r)[0]), "=r"((r)[1]), "=r"((r)[2]), "=r"((r)[3]) : "r"(addr))
#define MMA_FP16(d, a, b0, b1) \
    asm volatile("mma.sync.aligned.m16n8k16.row.col.f32.f16.f16.f32 " \
        "{%0,%1,%2,%3}, {%4,%5,%6,%7}, {%8,%9}, {%0,%1,%2,%3};" \
        : "+f"((d)[0]), "+f"((d)[1]), "+f"((d)[2]), "+f"((d)[3]) \
        : "r"((a)[0]), "r"((a)[1]), "r"((a)[2]), "r"((a)[3]), "r"(b0), "r"(b1))

// ---------------- 1) gather + add + LayerNorm -> fp16 ----------------------
__global__ void gather_ln(const float* __restrict__ x,
                          const int* __restrict__ src,
                          const int* __restrict__ dst,
                          const float* __restrict__ lnw,
                          __half* __restrict__ A, int E)
{
    __shared__ float sred[32];
    __shared__ float sbc;
    const int e = blockIdx.x;
    const int t = threadIdx.x;          // 128 threads, 4 floats each
    const size_t so = (size_t)src[e] * D;
    const size_t dofs = (size_t)dst[e] * D;

    float4 a = *(const float4*)(x + so + t * 4);
    float4 b = *(const float4*)(x + dofs + t * 4);
    float4 v = make_float4(a.x + b.x, a.y + b.y, a.z + b.z, a.w + b.w);

    const int lane = t & 31, wid = t >> 5;

    float s = v.x + v.y + v.z + v.w;
    #pragma unroll
    for (int o = 16; o; o >>= 1) s += __shfl_down_sync(0xffffffffu, s, o);
    if (lane == 0) sred[wid] = s;
    __syncthreads();
    if (t == 0) sbc = (sred[0] + sred[1] + sred[2] + sred[3]) * (1.0f / D);
    __syncthreads();
    const float mu = sbc;

    float dx = v.x - mu, dy = v.y - mu, dz = v.z - mu, dw = v.w - mu;
    float ss = dx * dx + dy * dy + dz * dz + dw * dw;
    __syncthreads();
    #pragma unroll
    for (int o = 16; o; o >>= 1) ss += __shfl_down_sync(0xffffffffu, ss, o);
    if (lane == 0) sred[wid] = ss;
    __syncthreads();
    if (t == 0) sbc = rsqrtf((sred[0] + sred[1] + sred[2] + sred[3]) * (1.0f / D) + EPSF);
    __syncthreads();
    const float rs = sbc;

    float4 w = *(const float4*)(lnw + t * 4);
    union { __half h[4]; uint2 u; } pk;
    pk.h[0] = __float2half(dx * rs * w.x);
    pk.h[1] = __float2half(dy * rs * w.y);
    pk.h[2] = __float2half(dz * rs * w.z);
    pk.h[3] = __float2half(dw * rs * w.w);
    *(uint2*)(A + (size_t)e * D + 4 * t) = pk.u;
}

// ---------------- weight convert: W[512,512] fp32 -> fp16 ------------------
__global__ void wconv(const float* __restrict__ W, __half* __restrict__ Wh)
{
    const int idx = blockIdx.x * blockDim.x + threadIdx.x;   // 512*512 threads
    Wh[idx] = __float2half(W[idx]);
}

// ---------------- BN+ReLU apply -> fp16 for next GEMM ----------------------
__global__ void bn_conv(const float* __restrict__ H, __half* __restrict__ A, int E)
{
    const int idx = blockIdx.x * blockDim.x + threadIdx.x;   // E*128 threads
    if (idx >= E * 128) return;
    const int r = idx >> 7;
    const int c = (idx & 127) * 4;
    float4 v = *(const float4*)(H + (size_t)r * D + c);
    float4 s4 = *(const float4*)(g_sc + c);
    float4 h4 = *(const float4*)(g_sh + c);
    union { __half h[4]; uint2 u; } pk;
    pk.h[0] = __float2half(fmaxf(fmaf(v.x, s4.x, h4.x), 0.0f));
    pk.h[1] = __float2half(fmaxf(fmaf(v.y, s4.y, h4.y), 0.0f));
    pk.h[2] = __float2half(fmaxf(fmaf(v.z, s4.z, h4.z), 0.0f));
    pk.h[3] = __float2half(fmaxf(fmaf(v.w, s4.w, h4.w), 0.0f));
    *(uint2*)(A + (size_t)r * D + c) = pk.u;
}

// ---------------- fp16 mma.sync GEMM + fused column stats ------------------
// C[M,512] = A[M,512] @ W^T (single-product fp16, fp32 accum); also
// accumulates per-column sum / sumsq of C into g_sum / g_sumsq.
// CTA tile 128x128, 8 warps (4Mx2N of 32x64 warp tiles) — proven R6 shape.
// 8 chunks of K=64, 3-stage cp.async pipeline, 2 CTAs/SM.
#define GEMM_SMEM (STAGES * 32768)

__global__ void __launch_bounds__(256, 2)
bgemm(const __half* __restrict__ A, const __half* __restrict__ W,
      float* __restrict__ C, int E)
{
    extern __shared__ __align__(128) char smem[];
    const int tid = threadIdx.x;
    const int lane = tid & 31, wid = tid >> 5;
    const int m0 = blockIdx.y * 128;
    const int n0 = blockIdx.x * 128;
    const uint32_t sbase = smem_to_u32(smem);

    // ---- cp.async mapping: thread -> (row = tid/2, 4 groups of 16B) ----
    const int lrow = tid >> 1;
    const int lg0  = (tid & 1) * 4;
    const __half* Abase = A + (size_t)(m0 + lrow) * D + lg0 * 8;
    const __half* Wbase = W + (size_t)(n0 + lrow) * D + lg0 * 8;
    uint32_t dsw[4];
    #pragma unroll
    for (int q = 0; q < 4; q++)
        dsw[q] = (uint32_t)(lrow * 128 + ((lg0 + q) ^ (lrow & 7)) * 16);

    // ---- ldmatrix fragment addresses (warp 32x64) ----
    const int wm = (wid & 3) * 32;        // warp M offset
    const int wn = (wid >> 2) * 64;       // warp N offset
    const int ar = wm + (lane & 15);                       // + mf*16
    const int agsel = lane >> 4;
    const int br = wn + (lane & 7) + ((lane >> 4) << 3);   // + np*16
    const int bgsel = (lane >> 3) & 1;

    float acc[2][8][4];
    #pragma unroll
    for (int i = 0; i < 2; i++)
        #pragma unroll
        for (int j = 0; j < 8; j++)
            #pragma unroll
            for (int q = 0; q < 4; q++) acc[i][j][q] = 0.0f;

    // issue chunk i (K offset i*64) into stage st
    auto issue = [&](int i, int st) {
        const char* aps = (const char*)(Abase + i * 64);
        const char* wps = (const char*)(Wbase + i * 64);
        const uint32_t da = sbase + st * STG_B;
        const uint32_t dw = da + 16384u;
        #pragma unroll
        for (int q = 0; q < 4; q++) {
            CP_ASYNC16(da + dsw[q], aps + q * 16);
            CP_ASYNC16(dw + dsw[q], wps + q * 16);
        }
        CP_COMMIT();
    };

    auto compute = [&](int st) {
        const uint32_t sA = sbase + st * STG_B;
        const uint32_t sW = sA + 16384u;
        #pragma unroll
        for (int kk = 0; kk < 4; kk++) {
            const int kg2 = kk * 2;
            uint32_t a[2][4];
            #pragma unroll
            for (int mf = 0; mf < 2; mf++) {
                const int r = ar + mf * 16;
                const int g = kg2 + agsel;
                LDM_X4(a[mf], sA + r * 128 + ((g ^ (r & 7)) * 16));
            }
            #pragma unroll
            for (int np = 0; np < 4; np++) {
                const int r = br + np * 16;
                const int g = kg2 + bgsel;
                uint32_t b[4];
                LDM_X4(b, sW + r * 128 + ((g ^ (r & 7)) * 16));
                #pragma unroll
                for (int mf = 0; mf < 2; mf++) {
                    MMA_FP16(acc[mf][np * 2],     a[mf], b[0], b[1]);
                    MMA_FP16(acc[mf][np * 2 + 1], a[mf], b[2], b[3]);
                }
            }
        }
    };

    // ---- 3-stage mainloop: wait -> barrier -> issue(i+2) -> compute(i) ----
    issue(0, 0);
    issue(1, 1);
    #pragma unroll 1
    for (int i = 0; i < CHUNKS; i++) {
        if (i < CHUNKS - 1)
            asm volatile("cp.async.wait_group 1;" ::: "memory");
        else
            asm volatile("cp.async.wait_group 0;" ::: "memory");
        __syncthreads();
        if (i + 2 < CHUNKS) issue(i + 2, (i + 2) % STAGES);
        compute(i % STAGES);
    }

    // ---- epilogue: fragment -> global fp32 ----
    const int cq = (lane & 3) * 2;
    const int rq = lane >> 2;
    #pragma unroll
    for (int mf = 0; mf < 2; mf++) {
        const int r0 = m0 + wm + mf * 16 + rq;
        #pragma unroll
        for (int nf = 0; nf < 8; nf++) {
            const int col = n0 + wn + nf * 8 + cq;
            if (r0 < E)
                *(float2*)(C + (size_t)r0 * D + col) =
                    make_float2(acc[mf][nf][0], acc[mf][nf][1]);
            if (r0 + 8 < E)
                *(float2*)(C + (size_t)(r0 + 8) * D + col) =
                    make_float2(acc[mf][nf][2], acc[mf][nf][3]);
        }
    }

    // ---- fused BN column stats (rows >= E are exactly zero in A) ----------
    float* ssum = (float*)smem;          // 128 floats
    float* ssq  = (float*)smem + 128;    // 128 floats
    __syncthreads();                     // pipeline smem reads all done
    if (tid < 128) { ssum[tid] = 0.0f; ssq[tid] = 0.0f; }
    __syncthreads();

    #pragma unroll
    for (int nf = 0; nf < 8; nf++) {
        #pragma unroll
        for (int p = 0; p < 2; p++) {
            float s = 0.0f, q = 0.0f;
            #pragma unroll
            for (int mf = 0; mf < 2; mf++) {
                float v0 = acc[mf][nf][p], v1 = acc[mf][nf][p + 2];
                s += v0 + v1;
                q += v0 * v0 + v1 * v1;
            }
            #pragma unroll
            for (int mk = 4; mk <= 16; mk <<= 1) {
                s += __shfl_xor_sync(0xffffffffu, s, mk);
                q += __shfl_xor_sync(0xffffffffu, q, mk);
            }
            if (lane < 4) {
                const int cl = wn + nf * 8 + (lane & 3) * 2 + p;
                atomicAdd(&ssum[cl], s);
                atomicAdd(&ssq[cl], q);
            }
        }
    }
    __syncthreads();
    if (tid < 128) {
        atomicAdd(&g_sum[n0 + tid], ssum[tid]);
        atomicAdd(&g_sumsq[n0 + tid], ssq[tid]);
    }
}

// ---------------- stats setup / finalize -----------------------------------
__global__ void zero_stats()
{
    const int c = threadIdx.x;
    g_sum[c] = 0.0f;
    g_sumsq[c] = 0.0f;
}

__global__ void finalize_stats(const float* __restrict__ g,
                               const float* __restrict__ b, float invE)
{
    const int c = threadIdx.x;
    const float mean = g_sum[c] * invE;
    const float var  = g_sumsq[c] * invE - mean * mean;
    const float istd = rsqrtf(var + EPSF);
    const float scv  = istd * g[c];
    g_sc[c] = scv;
    g_sh[c] = fmaf(-mean, scv, b[c]);
}

// ---------------- head: out[E,9] = relu(BN(H)) @ Wout^T --------------------
__global__ void head(const float* __restrict__ H,
                     const float* __restrict__ Wout,
                     float* __restrict__ out, int E)
{
    __shared__ float Ws[NCLS * D];
    for (int i = threadIdx.x; i < NCLS * D; i += blockDim.x) Ws[i] = Wout[i];
    __syncthreads();

    const int warp = threadIdx.x >> 5, lane = threadIdx.x & 31;
    const int row = blockIdx.x * 8 + warp;
    if (row >= E) return;

    const float* hp = H + (size_t)row * D;
    float acc[NCLS];
    #pragma unroll
    for (int j = 0; j < NCLS; j++) acc[j] = 0.0f;

    #pragma unroll
    for (int i = 0; i < D / 32; i++) {
        const int k = lane + i * 32;
        const float v = fmaxf(fmaf(hp[k], g_sc[k], g_sh[k]), 0.0f);
        #pragma unroll
        for (int j = 0; j < NCLS; j++) acc[j] = fmaf(v, Ws[j * D + k], acc[j]);
    }
    #pragma unroll
    for (int j = 0; j < NCLS; j++)
        #pragma unroll
        for (int o = 16; o; o >>= 1)
            acc[j] += __shfl_down_sync(0xffffffffu, acc[j], o);

    if (lane == 0) {
        #pragma unroll
        for (int j = 0; j < NCLS; j++) out[(size_t)row * NCLS + j] = acc[j];
    }
}

// ---------------- launch ---------------------------------------------------
extern "C" void kernel_launch(void* const* d_in, const int* in_sizes, int n_in,
                              void* d_out, int out_size)
{
    const float* x    = (const float*)d_in[0];
    const int*   src  = (const int*)d_in[1];
    const int*   dst  = (const int*)d_in[2];
    const float* lnw  = (const float*)d_in[3];
    const float* W1   = (const float*)d_in[4];
    const float* g1   = (const float*)d_in[5];
    const float* b1   = (const float*)d_in[6];
    const float* W2   = (const float*)d_in[7];
    const float* g2   = (const float*)d_in[8];
    const float* b2   = (const float*)d_in[9];
    const float* Wout = (const float*)d_in[10];
    float* out = (float*)d_out;

    const int E = in_sizes[1];
    const float invE = 1.0f / (float)E;
    const int mtiles = (E + 127) / 128;

    void *pa, *phb, *pw1, *pw2;
    cudaGetSymbolAddress(&pa, g_a);
    cudaGetSymbolAddress(&phb, g_h);
    cudaGetSymbolAddress(&pw1, g_w1h);
    cudaGetSymbolAddress(&pw2, g_w2h);

    cudaFuncSetAttribute(bgemm, cudaFuncAttributeMaxDynamicSharedMemorySize, GEMM_SMEM);

    float* h = (float*)phb;
    __half* A = (__half*)pa;

    // 1) gather + LN -> A (fp16); weight converts
    gather_ln<<<E, 128>>>(x, src, dst, lnw, A, E);
    wconv<<<512, 512>>>(W1, (__half*)pw1);
    wconv<<<512, 512>>>(W2, (__half*)pw2);

    // 2) GEMM1 (+ fused BN1 stats): h = A @ W1^T
    zero_stats<<<1, D>>>();
    bgemm<<<dim3(4, mtiles), 256, GEMM_SMEM>>>(A, (__half*)pw1, h, E);
    finalize_stats<<<1, D>>>(g1, b1, invE);

    // 3) BN1+ReLU apply -> A (fp16); GEMM2 (+ fused BN2 stats)
    bn_conv<<<(E * 128 + 255) / 256, 256>>>(h, A, E);
    zero_stats<<<1, D>>>();
    bgemm<<<dim3(4, mtiles), 256, GEMM_SMEM>>>(A, (__half*)pw2, h, E);
    finalize_stats<<<1, D>>>(g2, b2, invE);

    // 4) head
    head<<<(E + 7) / 8, 256>>>(h, Wout, out, E);
}

// round 11
// speedup vs baseline: 2.7932x; 1.0350x over previous
#include <cuda_runtime.h>
#include <cuda_fp16.h>
#include <cstdint>

#define D       512
#define NCLS    9
#define EPSF    1e-5f
#define E_PAD   150016   // 150000 padded to multiple of 128
#define CHUNKS  8        // K=512 in chunks of 64
#define STAGES  3
#define STG_B   32768u   // A 16KB + W 16KB per stage

// ---------------- scratch (bss; no runtime allocation) ---------------------
__device__ __align__(128) __half g_a[(size_t)E_PAD * D];   // A fp16
__device__ float g_h[(size_t)E_PAD * D];                   // GEMM fp32 out
__device__ __align__(128) __half g_w1h[512 * 512];         // W1 fp16
__device__ __align__(128) __half g_w2h[512 * 512];         // W2 fp16
__device__ float g_sum[D];
__device__ float g_sumsq[D];
__device__ float g_sc[D];
__device__ float g_sh[D];

// ======================= PTX helpers (sm_100-safe) ==========================
__device__ __forceinline__ uint32_t smem_to_u32(const void* p) {
    uint32_t a;
    asm("{ .reg .u64 t; cvta.to.shared.u64 t, %1; cvt.u32.u64 %0, t; }" : "=r"(a) : "l"(p));
    return a;
}
#define CP_ASYNC16(dst, src) \
    asm volatile("cp.async.cg.shared.global [%0], [%1], 16;" :: "r"(dst), "l"(src) : "memory")
#define CP_COMMIT() asm volatile("cp.async.commit_group;" ::: "memory")
#define LDM_X4(r, addr) \
    asm volatile("ldmatrix.sync.aligned.m8n8.x4.shared.b16 {%0,%1,%2,%3}, [%4];" \
        : "=r"((r)[0]), "=r"((r)[1]), "=r"((r)[2]), "=r"((r)[3]) : "r"(addr))
#define MMA_FP16(d, a, b0, b1) \
    asm volatile("mma.sync.aligned.m16n8k16.row.col.f32.f16.f16.f32 " \
        "{%0,%1,%2,%3}, {%4,%5,%6,%7}, {%8,%9}, {%0,%1,%2,%3};" \
        : "+f"((d)[0]), "+f"((d)[1]), "+f"((d)[2]), "+f"((d)[3]) \
        : "r"((a)[0]), "r"((a)[1]), "r"((a)[2]), "r"((a)[3]), "r"(b0), "r"(b1))

// ---------------- 1) gather + add + LayerNorm -> fp16 (warp per edge) ------
// One warp handles one edge: 16 floats/thread, shfl-only reductions.
// Block 0 also zeroes the BN1 stats accumulators (completes before bgemm1).
__global__ void gather_ln(const float* __restrict__ x,
                          const int* __restrict__ src,
                          const int* __restrict__ dst,
                          const float* __restrict__ lnw,
                          __half* __restrict__ A, int E)
{
    if (blockIdx.x == 0) {
        for (int c = threadIdx.x; c < D; c += blockDim.x) {
            g_sum[c] = 0.0f;
            g_sumsq[c] = 0.0f;
        }
    }
    const int e = (blockIdx.x * blockDim.x + threadIdx.x) >> 5;
    if (e >= E) return;
    const int lane = threadIdx.x & 31;

    const float* xs = x + (size_t)src[e] * D;
    const float* xd = x + (size_t)dst[e] * D;

    float4 v[4];
    float s = 0.0f;
    #pragma unroll
    for (int q = 0; q < 4; q++) {
        const int c = q * 128 + lane * 4;
        float4 a = *(const float4*)(xs + c);
        float4 b = *(const float4*)(xd + c);
        v[q] = make_float4(a.x + b.x, a.y + b.y, a.z + b.z, a.w + b.w);
        s += v[q].x + v[q].y + v[q].z + v[q].w;
    }
    #pragma unroll
    for (int o = 16; o; o >>= 1) s += __shfl_xor_sync(0xffffffffu, s, o);
    const float mu = s * (1.0f / D);

    float ss = 0.0f;
    #pragma unroll
    for (int q = 0; q < 4; q++) {
        v[q].x -= mu; v[q].y -= mu; v[q].z -= mu; v[q].w -= mu;
        ss += v[q].x * v[q].x + v[q].y * v[q].y + v[q].z * v[q].z + v[q].w * v[q].w;
    }
    #pragma unroll
    for (int o = 16; o; o >>= 1) ss += __shfl_xor_sync(0xffffffffu, ss, o);
    const float rs = rsqrtf(ss * (1.0f / D) + EPSF);

    __half* arow = A + (size_t)e * D;
    #pragma unroll
    for (int q = 0; q < 4; q++) {
        const int c = q * 128 + lane * 4;
        float4 w = *(const float4*)(lnw + c);
        union { __half h[4]; uint2 u; } pk;
        pk.h[0] = __float2half(v[q].x * rs * w.x);
        pk.h[1] = __float2half(v[q].y * rs * w.y);
        pk.h[2] = __float2half(v[q].z * rs * w.z);
        pk.h[3] = __float2half(v[q].w * rs * w.w);
        *(uint2*)(arow + c) = pk.u;
    }
}

// ---------------- weight convert: both W fp32 -> fp16 ----------------------
__global__ void wconv2(const float* __restrict__ W1, const float* __restrict__ W2,
                       __half* __restrict__ Wh1, __half* __restrict__ Wh2)
{
    const int idx = blockIdx.x * blockDim.x + threadIdx.x;   // 512*512 threads
    Wh1[idx] = __float2half(W1[idx]);
    Wh2[idx] = __float2half(W2[idx]);
}

// ---------------- BN+ReLU apply -> fp16 for next GEMM ----------------------
// Block 0 also zeroes stats for BN2 (g_sum already consumed by finalize_stats).
__global__ void bn_conv(const float* __restrict__ H, __half* __restrict__ A, int E)
{
    const int idx = blockIdx.x * blockDim.x + threadIdx.x;   // E*128 threads
    if (blockIdx.x == 0) {
        for (int c = threadIdx.x; c < D; c += blockDim.x) {
            g_sum[c] = 0.0f;
            g_sumsq[c] = 0.0f;
        }
    }
    if (idx >= E * 128) return;
    const int r = idx >> 7;
    const int c = (idx & 127) * 4;
    float4 v = *(const float4*)(H + (size_t)r * D + c);
    float4 s4 = *(const float4*)(g_sc + c);
    float4 h4 = *(const float4*)(g_sh + c);
    union { __half h[4]; uint2 u; } pk;
    pk.h[0] = __float2half(fmaxf(fmaf(v.x, s4.x, h4.x), 0.0f));
    pk.h[1] = __float2half(fmaxf(fmaf(v.y, s4.y, h4.y), 0.0f));
    pk.h[2] = __float2half(fmaxf(fmaf(v.z, s4.z, h4.z), 0.0f));
    pk.h[3] = __float2half(fmaxf(fmaf(v.w, s4.w, h4.w), 0.0f));
    *(uint2*)(A + (size_t)r * D + c) = pk.u;
}

// ---------------- fp16 mma.sync GEMM + fused column stats ------------------
// C[M,512] = A[M,512] @ W^T (fp16 in, fp32 accum); also accumulates
// per-column sum / sumsq of C into g_sum / g_sumsq.
// CTA tile 128x128, 8 warps (4Mx2N of 32x64 warp tiles) — proven shape.
// 8 chunks of K=64, 3-stage cp.async pipeline, 2 CTAs/SM.
#define GEMM_SMEM (STAGES * 32768)

__global__ void __launch_bounds__(256, 2)
bgemm(const __half* __restrict__ A, const __half* __restrict__ W,
      float* __restrict__ C, int E)
{
    extern __shared__ __align__(128) char smem[];
    const int tid = threadIdx.x;
    const int lane = tid & 31, wid = tid >> 5;
    const int m0 = blockIdx.y * 128;
    const int n0 = blockIdx.x * 128;
    const uint32_t sbase = smem_to_u32(smem);

    // ---- cp.async mapping: thread -> (row = tid/2, 4 groups of 16B) ----
    const int lrow = tid >> 1;
    const int lg0  = (tid & 1) * 4;
    const __half* Abase = A + (size_t)(m0 + lrow) * D + lg0 * 8;
    const __half* Wbase = W + (size_t)(n0 + lrow) * D + lg0 * 8;
    uint32_t dsw[4];
    #pragma unroll
    for (int q = 0; q < 4; q++)
        dsw[q] = (uint32_t)(lrow * 128 + ((lg0 + q) ^ (lrow & 7)) * 16);

    // ---- ldmatrix fragment addresses (warp 32x64) ----
    const int wm = (wid & 3) * 32;        // warp M offset
    const int wn = (wid >> 2) * 64;       // warp N offset
    const int ar = wm + (lane & 15);                       // + mf*16
    const int agsel = lane >> 4;
    const int br = wn + (lane & 7) + ((lane >> 4) << 3);   // + np*16
    const int bgsel = (lane >> 3) & 1;

    float acc[2][8][4];
    #pragma unroll
    for (int i = 0; i < 2; i++)
        #pragma unroll
        for (int j = 0; j < 8; j++)
            #pragma unroll
            for (int q = 0; q < 4; q++) acc[i][j][q] = 0.0f;

    // issue chunk i (K offset i*64) into stage st
    auto issue = [&](int i, int st) {
        const char* aps = (const char*)(Abase + i * 64);
        const char* wps = (const char*)(Wbase + i * 64);
        const uint32_t da = sbase + st * STG_B;
        const uint32_t dw = da + 16384u;
        #pragma unroll
        for (int q = 0; q < 4; q++) {
            CP_ASYNC16(da + dsw[q], aps + q * 16);
            CP_ASYNC16(dw + dsw[q], wps + q * 16);
        }
        CP_COMMIT();
    };

    auto compute = [&](int st) {
        const uint32_t sA = sbase + st * STG_B;
        const uint32_t sW = sA + 16384u;
        #pragma unroll
        for (int kk = 0; kk < 4; kk++) {
            const int kg2 = kk * 2;
            uint32_t a[2][4];
            #pragma unroll
            for (int mf = 0; mf < 2; mf++) {
                const int r = ar + mf * 16;
                const int g = kg2 + agsel;
                LDM_X4(a[mf], sA + r * 128 + ((g ^ (r & 7)) * 16));
            }
            #pragma unroll
            for (int np = 0; np < 4; np++) {
                const int r = br + np * 16;
                const int g = kg2 + bgsel;
                uint32_t b[4];
                LDM_X4(b, sW + r * 128 + ((g ^ (r & 7)) * 16));
                #pragma unroll
                for (int mf = 0; mf < 2; mf++) {
                    MMA_FP16(acc[mf][np * 2],     a[mf], b[0], b[1]);
                    MMA_FP16(acc[mf][np * 2 + 1], a[mf], b[2], b[3]);
                }
            }
        }
    };

    // ---- 3-stage mainloop: wait -> barrier -> issue(i+2) -> compute(i) ----
    issue(0, 0);
    issue(1, 1);
    #pragma unroll 1
    for (int i = 0; i < CHUNKS; i++) {
        if (i < CHUNKS - 1)
            asm volatile("cp.async.wait_group 1;" ::: "memory");
        else
            asm volatile("cp.async.wait_group 0;" ::: "memory");
        __syncthreads();
        if (i + 2 < CHUNKS) issue(i + 2, (i + 2) % STAGES);
        compute(i % STAGES);
    }

    // ---- epilogue: fragment -> global fp32 ----
    const int cq = (lane & 3) * 2;
    const int rq = lane >> 2;
    #pragma unroll
    for (int mf = 0; mf < 2; mf++) {
        const int r0 = m0 + wm + mf * 16 + rq;
        #pragma unroll
        for (int nf = 0; nf < 8; nf++) {
            const int col = n0 + wn + nf * 8 + cq;
            if (r0 < E)
                *(float2*)(C + (size_t)r0 * D + col) =
                    make_float2(acc[mf][nf][0], acc[mf][nf][1]);
            if (r0 + 8 < E)
                *(float2*)(C + (size_t)(r0 + 8) * D + col) =
                    make_float2(acc[mf][nf][2], acc[mf][nf][3]);
        }
    }

    // ---- fused BN column stats (rows >= E are exactly zero in A) ----------
    float* ssum = (float*)smem;          // 128 floats
    float* ssq  = (float*)smem + 128;    // 128 floats
    __syncthreads();                     // pipeline smem reads all done
    if (tid < 128) { ssum[tid] = 0.0f; ssq[tid] = 0.0f; }
    __syncthreads();

    #pragma unroll
    for (int nf = 0; nf < 8; nf++) {
        #pragma unroll
        for (int p = 0; p < 2; p++) {
            float s = 0.0f, q = 0.0f;
            #pragma unroll
            for (int mf = 0; mf < 2; mf++) {
                float v0 = acc[mf][nf][p], v1 = acc[mf][nf][p + 2];
                s += v0 + v1;
                q += v0 * v0 + v1 * v1;
            }
            #pragma unroll
            for (int mk = 4; mk <= 16; mk <<= 1) {
                s += __shfl_xor_sync(0xffffffffu, s, mk);
                q += __shfl_xor_sync(0xffffffffu, q, mk);
            }
            if (lane < 4) {
                const int cl = wn + nf * 8 + (lane & 3) * 2 + p;
                atomicAdd(&ssum[cl], s);
                atomicAdd(&ssq[cl], q);
            }
        }
    }
    __syncthreads();
    if (tid < 128) {
        atomicAdd(&g_sum[n0 + tid], ssum[tid]);
        atomicAdd(&g_sumsq[n0 + tid], ssq[tid]);
    }
}

// ---------------- stats finalize -------------------------------------------
__global__ void finalize_stats(const float* __restrict__ g,
                               const float* __restrict__ b, float invE)
{
    const int c = threadIdx.x;
    const float mean = g_sum[c] * invE;
    const float var  = g_sumsq[c] * invE - mean * mean;
    const float istd = rsqrtf(var + EPSF);
    const float scv  = istd * g[c];
    g_sc[c] = scv;
    g_sh[c] = fmaf(-mean, scv, b[c]);
}

// ---------------- head: out[E,9] = relu(BN(H)) @ Wout^T --------------------
__global__ void head(const float* __restrict__ H,
                     const float* __restrict__ Wout,
                     float* __restrict__ out, int E)
{
    __shared__ float Ws[NCLS * D];
    for (int i = threadIdx.x; i < NCLS * D; i += blockDim.x) Ws[i] = Wout[i];
    __syncthreads();

    const int warp = threadIdx.x >> 5, lane = threadIdx.x & 31;
    const int row = blockIdx.x * 8 + warp;
    if (row >= E) return;

    const float* hp = H + (size_t)row * D;
    float acc[NCLS];
    #pragma unroll
    for (int j = 0; j < NCLS; j++) acc[j] = 0.0f;

    #pragma unroll
    for (int i = 0; i < D / 32; i++) {
        const int k = lane + i * 32;
        const float v = fmaxf(fmaf(hp[k], g_sc[k], g_sh[k]), 0.0f);
        #pragma unroll
        for (int j = 0; j < NCLS; j++) acc[j] = fmaf(v, Ws[j * D + k], acc[j]);
    }
    #pragma unroll
    for (int j = 0; j < NCLS; j++)
        #pragma unroll
        for (int o = 16; o; o >>= 1)
            acc[j] += __shfl_down_sync(0xffffffffu, acc[j], o);

    if (lane == 0) {
        #pragma unroll
        for (int j = 0; j < NCLS; j++) out[(size_t)row * NCLS + j] = acc[j];
    }
}

// ---------------- launch ---------------------------------------------------
extern "C" void kernel_launch(void* const* d_in, const int* in_sizes, int n_in,
                              void* d_out, int out_size)
{
    const float* x    = (const float*)d_in[0];
    const int*   src  = (const int*)d_in[1];
    const int*   dst  = (const int*)d_in[2];
    const float* lnw  = (const float*)d_in[3];
    const float* W1   = (const float*)d_in[4];
    const float* g1   = (const float*)d_in[5];
    const float* b1   = (const float*)d_in[6];
    const float* W2   = (const float*)d_in[7];
    const float* g2   = (const float*)d_in[8];
    const float* b2   = (const float*)d_in[9];
    const float* Wout = (const float*)d_in[10];
    float* out = (float*)d_out;

    const int E = in_sizes[1];
    const float invE = 1.0f / (float)E;
    const int mtiles = (E + 127) / 128;

    void *pa, *phb, *pw1, *pw2;
    cudaGetSymbolAddress(&pa, g_a);
    cudaGetSymbolAddress(&phb, g_h);
    cudaGetSymbolAddress(&pw1, g_w1h);
    cudaGetSymbolAddress(&pw2, g_w2h);

    cudaFuncSetAttribute(bgemm, cudaFuncAttributeMaxDynamicSharedMemorySize, GEMM_SMEM);

    float* h = (float*)phb;
    __half* A = (__half*)pa;

    // 1) gather + LN -> A (fp16), zeroes BN1 stats; weight converts
    gather_ln<<<(E + 7) / 8, 256>>>(x, src, dst, lnw, A, E);
    wconv2<<<512, 512>>>(W1, W2, (__half*)pw1, (__half*)pw2);

    // 2) GEMM1 (+ fused BN1 stats): h = A @ W1^T
    bgemm<<<dim3(4, mtiles), 256, GEMM_SMEM>>>(A, (__half*)pw1, h, E);
    finalize_stats<<<1, D>>>(g1, b1, invE);

    // 3) BN1+ReLU apply -> A (fp16), zeroes BN2 stats; GEMM2 (+ fused stats)
    bn_conv<<<(E * 128 + 255) / 256, 256>>>(h, A, E);
    bgemm<<<dim3(4, mtiles), 256, GEMM_SMEM>>>(A, (__half*)pw2, h, E);
    finalize_stats<<<1, D>>>(g2, b2, invE);

    // 4) head
    head<<<(E + 7) / 8, 256>>>(h, Wout, out, E);
}